// round 8
// baseline (speedup 1.0000x reference)
#include <cuda_runtime.h>
#include <cstdint>

typedef unsigned long long ull;

#define H     51
#define TSEQ  512
#define FUT   64
#define TTOT  (TSEQ + FUT)
#define BB    8
#define NT    512          // 16 warps = 2 j-slices x 8 k-splits
#define NKS   8
#define GROW  260
#define HROW  228          // h dup row: slots 0..50=h1, 51..101=h2, pad..113
#define INROW 516
#define SZ_G  (BB*GROW)    // 2080
#define P1    4            // L1 k-pairs per warp (K padded 51->64)
#define P2    7            // L2 k-pairs per warp (K padded 102->112)

// ---- smem layout (float offsets) ----
#define OFF_WX  0           // 208 (interleaved col 4u+g)
#define OFF_B1  208
#define OFF_B2  416
#define OFF_WL  624         // 64
#define OFF_IN  688         // 8*516 = 4128
#define OFF_HD  4816        // 1840 (8*228 + pad)
#define SZ_HD   1840
#define OFF_G   6656        // 8*2080 = 16640
#define OFF_OUT (OFF_G + NKS*SZ_G)   // 23296
#define OFF_BL  (OFF_OUT + 8)
#define SMEM_FLOATS (OFF_BL + 4)     // 23308 -> 93232 B
#define SMEM_BYTES  (SMEM_FLOATS * 4)

__device__ __forceinline__ ull ffma2(ull a, ull b, ull c) {
    ull d;
    asm("fma.rn.f32x2 %0, %1, %2, %3;" : "=l"(d) : "l"(a), "l"(b), "l"(c));
    return d;
}

__device__ __forceinline__ ull pk(float a, float b) {
    ull r;
    unsigned ua = __float_as_uint(a), ub = __float_as_uint(b);
    asm("mov.b64 %0, {%1, %2};" : "=l"(r) : "r"(ua), "r"(ub));  // a = low
    return r;
}

__device__ __forceinline__ float frcp(float x) {
    float r;
    asm("rcp.approx.f32 %0, %1;" : "=f"(r) : "f"(x));
    return r;
}

// weight fetch (one-time): interleaved col = 4u+g <-> row g*H+u
__device__ __forceinline__ float w1f(const float* __restrict__ Whh1,
                                     int u, int g, int k) {
    return (u < H && k < H) ? Whh1[(g*H + u)*H + k] : 0.0f;
}
__device__ __forceinline__ float w2f(const float* __restrict__ Wih2,
                                     const float* __restrict__ Whh2,
                                     int u, int g, int k) {
    if (u >= H) return 0.0f;
    int row = (g*H + u)*H;
    if (k < H)   return Wih2[row + k];
    if (k < 2*H) return Whh2[row + (k - H)];
    return 0.0f;
}

// LSTM cell update, 5 EX2 + 2 RCP (common-denominator form).
// c' = c/(1+ef) + sign(gg)(1-eg)/((1+ei)(1+eg));  h = sig(go)*tanh(c')
__device__ __forceinline__ float cellup(float gi, float gf, float gg, float go,
                                        float& c)
{
    const float L2E = 1.4426950408889634f;
    float ei = exp2f(-L2E * gi);
    float ef = exp2f(-L2E * gf);
    float eg = exp2f(-2.0f * L2E * fabsf(gg));
    float pi = 1.0f + ei, pf = 1.0f + ef, pg = 1.0f + eg;
    float tg = copysignf(1.0f - eg, gg);
    float num = c * pi * pg + tg * pf;
    c = num * frcp(pf * pi * pg);
    float eo = exp2f(-L2E * go);
    float ec = exp2f(-2.0f * L2E * fabsf(c));
    return copysignf(1.0f - ec, c) * frcp((1.0f + eo) * (1.0f + ec));
}

// matvec with register-resident weights: NP k-pairs, 2 passes of 4 batches.
template<int NP>
__device__ __forceinline__ void mv_reg(const ull w[NP][4],
                                       const float* __restrict__ hbase,
                                       float* __restrict__ gout, int j0)
{
    #pragma unroll
    for (int pass = 0; pass < 2; ++pass) {
        const int bo = pass * 4;
        ull a0[4], a1[4];
        #pragma unroll
        for (int i = 0; i < 4; ++i) { a0[i] = 0ull; a1[i] = 0ull; }
        #pragma unroll
        for (int p = 0; p < NP; ++p) {
            #pragma unroll
            for (int i = 0; i < 4; ++i) {
                ulonglong2 hv = *reinterpret_cast<const ulonglong2*>(
                    hbase + (bo + i)*HROW + 4*p);
                a0[i] = ffma2(w[p][0], hv.x, a0[i]);
                a1[i] = ffma2(w[p][1], hv.x, a1[i]);
                a0[i] = ffma2(w[p][2], hv.y, a0[i]);
                a1[i] = ffma2(w[p][3], hv.y, a1[i]);
            }
        }
        #pragma unroll
        for (int i = 0; i < 4; ++i)
            *reinterpret_cast<ulonglong2*>(gout + (bo + i)*GROW + j0) =
                make_ulonglong2(a0[i], a1[i]);
    }
}

__global__ void __launch_bounds__(NT, 1)
lstm_seq_kernel(const float* __restrict__ input,
                const float* __restrict__ Wih1, const float* __restrict__ Whh1,
                const float* __restrict__ bih1, const float* __restrict__ bhh1,
                const float* __restrict__ Wih2, const float* __restrict__ Whh2,
                const float* __restrict__ bih2, const float* __restrict__ bhh2,
                const float* __restrict__ Wl,   const float* __restrict__ bl,
                float* __restrict__ out)
{
    extern __shared__ __align__(16) float sm[];
    const int tid = threadIdx.x;
    const int b0  = blockIdx.x * BB;

    // ---------- one-time prep ----------
    for (int j = tid; j < 208; j += NT) {
        float wx = 0.f, v1 = 0.f, v2 = 0.f;
        if (j < 4*H) {
            int row = (j & 3)*H + (j >> 2);
            wx = Wih1[row];
            v1 = bih1[row] + bhh1[row];
            v2 = bih2[row] + bhh2[row];
        }
        sm[OFF_WX + j] = wx;
        sm[OFF_B1 + j] = v1;
        sm[OFF_B2 + j] = v2;
    }
    if (tid < 64) sm[OFF_WL + tid] = (tid < H) ? Wl[tid] : 0.0f;
    for (int idx = tid; idx < BB*TSEQ; idx += NT) {
        int b = idx >> 9, t = idx & 511;
        sm[OFF_IN + b*INROW + t] = input[b0*TSEQ + idx];
    }
    for (int idx = tid; idx < SZ_HD; idx += NT) sm[OFF_HD + idx] = 0.0f;
    if (tid < 8)  sm[OFF_OUT + tid] = 0.0f;
    if (tid == 0) sm[OFF_BL] = bl[0];

    // ---------- roles ----------
    const int wid  = tid >> 5, lane = tid & 31;
    const int js   = wid & 1;            // j-slice
    const int kh   = wid >> 1;           // k-split (0..7)
    const int u    = js*32 + lane;       // unit (0..63; >=51 pad)
    const int j0   = 4*u;                // 4 cols = unit's (i,f,g,o)
    float* gout = sm + OFF_G + kh*SZ_G;

    // ---------- weight registers (global -> reg, one time) ----------
    ull w1r[P1][4], w2r[P2][4];
    #pragma unroll
    for (int p = 0; p < P1; ++p) {
        int kp = kh*P1 + p;
        #pragma unroll
        for (int d = 0; d < 2; ++d) {
            int k = 2*kp + d;
            w1r[p][2*d+0] = pk(w1f(Whh1, u, 0, k), w1f(Whh1, u, 1, k));
            w1r[p][2*d+1] = pk(w1f(Whh1, u, 2, k), w1f(Whh1, u, 3, k));
        }
    }
    #pragma unroll
    for (int p = 0; p < P2; ++p) {
        int kp = kh*P2 + p;
        #pragma unroll
        for (int d = 0; d < 2; ++d) {
            int k = 2*kp + d;
            w2r[p][2*d+0] = pk(w2f(Wih2, Whh2, u, 0, k), w2f(Wih2, Whh2, u, 1, k));
            w2r[p][2*d+1] = pk(w2f(Wih2, Whh2, u, 2, k), w2f(Wih2, Whh2, u, 3, k));
        }
    }

    // gates role: task (gb, gh) for tid < 408
    const int gb = tid & 7, gh = tid >> 3;
    const bool gact = (tid < BB*H);
    const float* gxin = sm + OFF_IN + gb*INROW;
    float c1 = 0.f, c2 = 0.f;

    float* hd = sm + OFF_HD;
    const float* h1base = hd + kh*(4*P1);   // L1 k-window start (dup offsets)
    const float* h2base = hd + kh*(4*P2);   // L2 k-window start

    __syncthreads();

    for (int t = 0; t < TTOT; ++t) {
        // ---- matvec layer 1 (register weights; pure Whh1 @ h1) ----
        mv_reg<P1>(w1r, h1base, gout, j0);
        __syncthreads();

        // ---- gates layer 1: 8-split reduce + x*Wih1 + bias + cell update ----
        if (gact) {
            const float* gp = sm + OFF_G + gb*GROW + 4*gh;
            float4 s0 = *reinterpret_cast<const float4*>(gp);
            float4 s1 = *reinterpret_cast<const float4*>(gp + SZ_G);
            float4 s2 = *reinterpret_cast<const float4*>(gp + 2*SZ_G);
            float4 s3 = *reinterpret_cast<const float4*>(gp + 3*SZ_G);
            float4 s4 = *reinterpret_cast<const float4*>(gp + 4*SZ_G);
            float4 s5 = *reinterpret_cast<const float4*>(gp + 5*SZ_G);
            float4 s6 = *reinterpret_cast<const float4*>(gp + 6*SZ_G);
            float4 s7 = *reinterpret_cast<const float4*>(gp + 7*SZ_G);
            float x  = (t < TSEQ) ? gxin[t] : sm[OFF_OUT + gb];
            float4 wx = *reinterpret_cast<const float4*>(sm + OFF_WX + 4*gh);
            float4 bb = *reinterpret_cast<const float4*>(sm + OFF_B1 + 4*gh);
            float gi = ((s0.x+s1.x)+(s2.x+s3.x)) + ((s4.x+s5.x)+(s6.x+s7.x)) + fmaf(x, wx.x, bb.x);
            float gf = ((s0.y+s1.y)+(s2.y+s3.y)) + ((s4.y+s5.y)+(s6.y+s7.y)) + fmaf(x, wx.y, bb.y);
            float gg = ((s0.z+s1.z)+(s2.z+s3.z)) + ((s4.z+s5.z)+(s6.z+s7.z)) + fmaf(x, wx.z, bb.z);
            float go = ((s0.w+s1.w)+(s2.w+s3.w)) + ((s4.w+s5.w)+(s6.w+s7.w)) + fmaf(x, wx.w, bb.w);
            float hn = cellup(gi, gf, gg, go, c1);
            *reinterpret_cast<float2*>(hd + gb*HROW + 2*gh) = make_float2(hn, hn);
        }
        __syncthreads();

        // ---- matvec layer 2 ([Wih2|Whh2] @ [h1;h2]) ----
        mv_reg<P2>(w2r, h2base, gout, j0);
        __syncthreads();

        // ---- gates layer 2 ----
        if (gact) {
            const float* gp = sm + OFF_G + gb*GROW + 4*gh;
            float4 s0 = *reinterpret_cast<const float4*>(gp);
            float4 s1 = *reinterpret_cast<const float4*>(gp + SZ_G);
            float4 s2 = *reinterpret_cast<const float4*>(gp + 2*SZ_G);
            float4 s3 = *reinterpret_cast<const float4*>(gp + 3*SZ_G);
            float4 s4 = *reinterpret_cast<const float4*>(gp + 4*SZ_G);
            float4 s5 = *reinterpret_cast<const float4*>(gp + 5*SZ_G);
            float4 s6 = *reinterpret_cast<const float4*>(gp + 6*SZ_G);
            float4 s7 = *reinterpret_cast<const float4*>(gp + 7*SZ_G);
            float4 bb = *reinterpret_cast<const float4*>(sm + OFF_B2 + 4*gh);
            float gi = ((s0.x+s1.x)+(s2.x+s3.x)) + ((s4.x+s5.x)+(s6.x+s7.x)) + bb.x;
            float gf = ((s0.y+s1.y)+(s2.y+s3.y)) + ((s4.y+s5.y)+(s6.y+s7.y)) + bb.y;
            float gg = ((s0.z+s1.z)+(s2.z+s3.z)) + ((s4.z+s5.z)+(s6.z+s7.z)) + bb.z;
            float go = ((s0.w+s1.w)+(s2.w+s3.w)) + ((s4.w+s5.w)+(s6.w+s7.w)) + bb.w;
            float hn = cellup(gi, gf, gg, go, c2);
            *reinterpret_cast<float2*>(hd + gb*HROW + 2*(H + gh)) = make_float2(hn, hn);
        }
        __syncthreads();

        // ---- output: warps 0-7, batch = wid ----
        if (wid < 8) {
            const float* h2p = hd + wid*HROW + 2*H;
            float p = h2p[2*lane] * sm[OFF_WL + lane];
            if (lane + 32 < H)
                p += h2p[2*(lane + 32)] * sm[OFF_WL + lane + 32];
            #pragma unroll
            for (int o = 16; o > 0; o >>= 1)
                p += __shfl_xor_sync(0xffffffffu, p, o);
            if (lane == 0) {
                float ov = p + sm[OFF_BL];
                out[(b0 + wid)*TTOT + t] = ov;
                sm[OFF_OUT + wid] = ov;        // consumed when t+1 >= TSEQ
            }
        }
        if (t >= TSEQ - 1) __syncthreads();    // protect OFF_OUT (future phase)
    }
}

extern "C" void kernel_launch(void* const* d_in, const int* in_sizes, int n_in,
                              void* d_out, int out_size)
{
    (void)n_in; (void)out_size;
    cudaFuncSetAttribute(lstm_seq_kernel,
                         cudaFuncAttributeMaxDynamicSharedMemorySize, SMEM_BYTES);
    int nblocks = in_sizes[0] / (TSEQ * BB);   // B / 8 = 128
    lstm_seq_kernel<<<nblocks, NT, SMEM_BYTES>>>(
        (const float*)d_in[0],  (const float*)d_in[1], (const float*)d_in[2],
        (const float*)d_in[3],  (const float*)d_in[4], (const float*)d_in[5],
        (const float*)d_in[6],  (const float*)d_in[7], (const float*)d_in[8],
        (const float*)d_in[9],  (const float*)d_in[10],
        (float*)d_out);
}

// round 9
// speedup vs baseline: 1.1214x; 1.1214x over previous
#include <cuda_runtime.h>
#include <cstdint>

typedef unsigned long long ull;

#define H     51
#define GP    208         // gate cols (204 real, interleaved col = 4u+g)
#define GROW  212         // split-buffer row stride
#define SZ_G  (8*GROW)    // 1696
#define HR    116         // h dup row stride (h1 and h2 buffers)
#define TSEQ  512
#define FUT   64
#define TTOT  (TSEQ + FUT)
#define NT    256         // 8 warps = 2 j-slices x 4 k-splits
#define INROW 516

// ---- smem layout (float offsets) ----
#define OFF_W1T 0                         // 56 x 208 (K padded 52->56)
#define SZ_W1T  (56*GP)
#define OFF_W2T (OFF_W1T + SZ_W1T)        // 104 x 208
#define SZ_W2T  (104*GP)
#define OFF_WX  (OFF_W2T + SZ_W2T)
#define OFF_B1  (OFF_WX + GP)
#define OFF_B2  (OFF_B1 + GP)
#define OFF_WL  (OFF_B2 + GP)
#define OFF_IN  (OFF_WL + 64)
#define OFF_H1  (OFF_IN + 8*INROW)
#define OFF_H2  (OFF_H1 + 8*HR)
#define OFF_G1  (OFF_H2 + 8*HR)
#define OFF_G2  (OFF_G1 + 4*SZ_G)
#define OFF_OUT (OFF_G2 + 4*SZ_G)
#define OFF_BL  (OFF_OUT + 8)
#define SMEM_FLOATS (OFF_BL + 4)          // ~53544 -> ~214 KB
#define SMEM_BYTES  (SMEM_FLOATS * 4)

__device__ __forceinline__ ull ffma2(ull a, ull b, ull c) {
    ull d;
    asm("fma.rn.f32x2 %0, %1, %2, %3;" : "=l"(d) : "l"(a), "l"(b), "l"(c));
    return d;
}

__device__ __forceinline__ float fsig(float x) {
    float e = __expf(-x);
    return __fdividef(1.0f, 1.0f + e);
}

__device__ __forceinline__ float ftanh_acc(float x) {
    float a = fabsf(x);
    float e = __expf(-2.0f * a);
    float r = __fdividef(1.0f - e, 1.0f + e);
    return copysignf(r, x);
}

template<int NP>
__device__ __forceinline__ void mv(const float* __restrict__ WT,
                                   const float* __restrict__ hb,
                                   float* __restrict__ gout, int j0)
{
    ull a0[8], a1[8];
    #pragma unroll
    for (int b = 0; b < 8; ++b) { a0[b] = 0ull; a1[b] = 0ull; }
    #pragma unroll
    for (int kp = 0; kp < NP; ++kp) {
        ulonglong2 w0 = *reinterpret_cast<const ulonglong2*>(WT + (2*kp  )*GP + j0);
        ulonglong2 w1 = *reinterpret_cast<const ulonglong2*>(WT + (2*kp+1)*GP + j0);
        #pragma unroll
        for (int b = 0; b < 8; ++b) {
            ulonglong2 hv = *reinterpret_cast<const ulonglong2*>(hb + b*HR + 4*kp);
            a0[b] = ffma2(w0.x, hv.x, a0[b]);
            a1[b] = ffma2(w0.y, hv.x, a1[b]);
            a0[b] = ffma2(w1.x, hv.y, a0[b]);
            a1[b] = ffma2(w1.y, hv.y, a1[b]);
        }
    }
    #pragma unroll
    for (int b = 0; b < 8; ++b)
        *reinterpret_cast<ulonglong2*>(gout + b*GROW + j0) =
            make_ulonglong2(a0[b], a1[b]);
}

// gate tasks for one layer over split buffers gbase (4 splits), optional x.
__device__ __forceinline__ void gate_tasks(const float* __restrict__ sm,
                                           const float* __restrict__ gbase,
                                           const float* __restrict__ bias,
                                           float* __restrict__ Hdst,
                                           float creg[2], int tid,
                                           bool withx, float x0, float x1)
{
    #pragma unroll
    for (int rep = 0; rep < 2; ++rep) {
        int tt = tid + rep*NT;
        if (tt < 8*H) {
            int b = tt & 7, hu = tt >> 3;
            const float* gp = gbase + b*GROW + 4*hu;
            float4 s0 = *reinterpret_cast<const float4*>(gp);
            float4 s1 = *reinterpret_cast<const float4*>(gp + SZ_G);
            float4 s2 = *reinterpret_cast<const float4*>(gp + 2*SZ_G);
            float4 s3 = *reinterpret_cast<const float4*>(gp + 3*SZ_G);
            float4 bb = *reinterpret_cast<const float4*>(bias + 4*hu);
            float gi = (s0.x+s1.x)+(s2.x+s3.x) + bb.x;
            float gf = (s0.y+s1.y)+(s2.y+s3.y) + bb.y;
            float gg = (s0.z+s1.z)+(s2.z+s3.z) + bb.z;
            float go = (s0.w+s1.w)+(s2.w+s3.w) + bb.w;
            if (withx) {
                float x = rep ? x1 : x0;
                float4 wx = *reinterpret_cast<const float4*>(sm + OFF_WX + 4*hu);
                gi = fmaf(x, wx.x, gi);
                gf = fmaf(x, wx.y, gf);
                gg = fmaf(x, wx.z, gg);
                go = fmaf(x, wx.w, go);
            }
            float& c = creg[rep];
            c = fsig(gf)*c + fsig(gi)*ftanh_acc(gg);
            float hn = fsig(go)*ftanh_acc(c);
            *reinterpret_cast<float2*>(Hdst + b*HR + 2*hu) = make_float2(hn, hn);
        }
    }
}

__device__ __forceinline__ void out_reduce(const float* __restrict__ sm,
                                           const float* __restrict__ H2,
                                           float* __restrict__ smw,
                                           float* __restrict__ out,
                                           int wid, int lane, int b0, int tp,
                                           bool feed)
{
    const float* h2p = H2 + wid*HR;
    float p = h2p[2*lane] * sm[OFF_WL + lane];
    if (lane + 32 < H) p += h2p[2*(lane+32)] * sm[OFF_WL + lane + 32];
    #pragma unroll
    for (int o = 16; o > 0; o >>= 1)
        p += __shfl_xor_sync(0xffffffffu, p, o);
    if (lane == 0) {
        float ov = p + sm[OFF_BL];
        out[(b0 + wid)*TTOT + tp] = ov;
        if (feed) smw[wid] = ov;
    }
}

__global__ void __launch_bounds__(NT, 1)
lstm_seq_kernel(const float* __restrict__ input,
                const float* __restrict__ Wih1, const float* __restrict__ Whh1,
                const float* __restrict__ bih1, const float* __restrict__ bhh1,
                const float* __restrict__ Wih2, const float* __restrict__ Whh2,
                const float* __restrict__ bih2, const float* __restrict__ bhh2,
                const float* __restrict__ Wl,   const float* __restrict__ bl,
                float* __restrict__ out)
{
    extern __shared__ __align__(16) float sm[];
    const int tid = threadIdx.x;
    const int b0  = blockIdx.x * 8;

    // ---------- one-time prep ----------
    for (int idx = tid; idx < SZ_W1T; idx += NT) {
        int k = idx / GP, j = idx % GP;
        int u = j >> 2, g = j & 3;
        sm[OFF_W1T + idx] = (u < H && k < H) ? Whh1[(g*H + u)*H + k] : 0.0f;
    }
    for (int idx = tid; idx < SZ_W2T; idx += NT) {
        int k = idx / GP, j = idx % GP;
        int u = j >> 2, g = j & 3;
        float v = 0.0f;
        if (u < H) {
            int row = (g*H + u)*H;
            if (k < H)                   v = Wih2[row + k];
            else if (k >= 52 && k < 103) v = Whh2[row + (k - 52)];
        }
        sm[OFF_W2T + idx] = v;
    }
    for (int j = tid; j < GP; j += NT) {
        int u = j >> 2, g = j & 3;
        float wx = 0.f, v1 = 0.f, v2 = 0.f;
        if (u < H) {
            int row = g*H + u;
            wx = Wih1[row];
            v1 = bih1[row] + bhh1[row];
            v2 = bih2[row] + bhh2[row];
        }
        sm[OFF_WX + j] = wx;
        sm[OFF_B1 + j] = v1;
        sm[OFF_B2 + j] = v2;
    }
    if (tid < 64) sm[OFF_WL + tid] = (tid < H) ? Wl[tid] : 0.0f;
    for (int idx = tid; idx < 8*TSEQ; idx += NT) {
        int b = idx >> 9, tt = idx & 511;
        sm[OFF_IN + b*INROW + tt] = input[b0*TSEQ + idx];
    }
    for (int idx = tid; idx < 16*HR; idx += NT) sm[OFF_H1 + idx] = 0.0f;
    for (int idx = tid; idx < 8*SZ_G; idx += NT) sm[OFF_G1 + idx] = 0.0f;
    if (tid < 8)  sm[OFF_OUT + tid] = 0.0f;
    if (tid == 0) sm[OFF_BL] = bl[0];
    __syncthreads();

    // ---------- roles ----------
    const int wid  = tid >> 5, lane = tid & 31;
    const int js   = wid & 1;
    const int kh   = wid >> 1;
    const bool mact = (lane < 26);
    const int j0   = 4*(js*26 + lane);

    const float* W1 = sm + OFF_W1T + (14*kh)*GP;
    const float* W2 = sm + OFF_W2T + (26*kh)*GP;
    const float* h1mv1 = sm + OFF_H1 + 28*kh;
    const float* hmv2  = (kh < 2) ? sm + OFF_H1 + 52*kh
                                  : sm + OFF_H2 + 52*(kh - 2);
    float* g1out = sm + OFF_G1 + kh*SZ_G;
    float* g2out = sm + OFF_G2 + kh*SZ_G;

    float* H1 = sm + OFF_H1;
    float* H2 = sm + OFF_H2;
    float c1r[2] = {0.f, 0.f};
    float c2r[2] = {0.f, 0.f};
    const int gb0 = tid & 7;
    const int gb1 = (tid + NT) & 7;        // == gb0 (NT mult of 8); kept for clarity

    for (int t = 0; t < TTOT; ++t) {
        // future-only pre-phase: g2(t-1) then out(t-1) so x(t) exists
        if (t >= TSEQ) {
            gate_tasks(sm, sm + OFF_G2, sm + OFF_B2, H2, c2r, tid,
                       false, 0.f, 0.f);
            __syncthreads();
            out_reduce(sm, H2, sm + OFF_OUT, out, wid, lane, b0, t-1, true);
            __syncthreads();
        }

        // G phase: g1(t) [+ g2(t-1) in main region]
        {
            float x0 = (t < TSEQ) ? sm[OFF_IN + gb0*INROW + t] : sm[OFF_OUT + gb0];
            float x1 = (t < TSEQ) ? sm[OFF_IN + gb1*INROW + t] : sm[OFF_OUT + gb1];
            gate_tasks(sm, sm + OFF_G1, sm + OFF_B1, H1, c1r, tid,
                       true, x0, x1);
        }
        if (t > 0 && t < TSEQ)
            gate_tasks(sm, sm + OFF_G2, sm + OFF_B2, H2, c2r, tid,
                       false, 0.f, 0.f);
        __syncthreads();

        // M phase: mv2(t) + mv1(t+1) + out(t-1)
        if (mact) {
            mv<13>(W2, hmv2, g2out, j0);
            mv<7>(W1, h1mv1, g1out, j0);
        }
        if (t > 0 && t < TSEQ)
            out_reduce(sm, H2, sm + OFF_OUT, out, wid, lane, b0, t-1, false);
        __syncthreads();
    }

    // epilogue: g2(TTOT-1) + out(TTOT-1)
    gate_tasks(sm, sm + OFF_G2, sm + OFF_B2, H2, c2r, tid, false, 0.f, 0.f);
    __syncthreads();
    out_reduce(sm, H2, sm + OFF_OUT, out, wid, lane, b0, TTOT-1, false);
}

extern "C" void kernel_launch(void* const* d_in, const int* in_sizes, int n_in,
                              void* d_out, int out_size)
{
    (void)n_in; (void)out_size;
    cudaFuncSetAttribute(lstm_seq_kernel,
                         cudaFuncAttributeMaxDynamicSharedMemorySize, SMEM_BYTES);
    int nblocks = in_sizes[0] / (TSEQ * 8);   // B / 8 = 128
    lstm_seq_kernel<<<nblocks, NT, SMEM_BYTES>>>(
        (const float*)d_in[0],  (const float*)d_in[1], (const float*)d_in[2],
        (const float*)d_in[3],  (const float*)d_in[4], (const float*)d_in[5],
        (const float*)d_in[6],  (const float*)d_in[7], (const float*)d_in[8],
        (const float*)d_in[9],  (const float*)d_in[10],
        (float*)d_out);
}